// round 17
// baseline (speedup 1.0000x reference)
#include <cuda_runtime.h>
#include <math.h>

#define Bn 64
#define Dn 8732
#define Qn 2183      // Dn/4, defaults per match block
#define On 16
#define Cn 81

// ---- device scratch (no allocations; all write-before-read each launch) ----
__device__ float g_loc_arr[Bn];
__device__ float g_pos_arr[Bn];
__device__ float g_neg_arr[Bn];
__device__ int   g_npos[Bn];
__device__ unsigned long long g_objbest[Bn * 4 * On];  // per-quarter packed (iou_bits<<32)|(~d)
__device__ float g_negce[Bn * Dn];                     // lse - p[0] (ce for negatives)
__device__ unsigned char g_obj[Bn * Dn];
__device__ unsigned char g_lab[Bn * Dn];               // resolved target label (0..80)

__device__ __forceinline__ float ex2f(float x) {
    float y; asm("ex2.approx.f32 %0, %1;" : "=f"(y) : "f"(x)); return y;
}

// 4 blocks per batch element; block handles a quarter of the defaults.
// Division-free (inter,union) cross-multiplication comparisons.
// Per-quarter object-best via PLAIN STORE (no init kernel needed).
__global__ __launch_bounds__(512) void k_match(const float* __restrict__ boxes,
                                               const int*   __restrict__ labels,
                                               const float* __restrict__ dboxes) {
    __shared__ float s_bx[On][4];
    __shared__ float s_area[On];
    __shared__ int   s_lab[On];
    __shared__ float s_redn[On * 16];
    __shared__ float s_redd[On * 16];
    __shared__ int   s_redi[On * 16];

    const int b    = blockIdx.x >> 2;
    const int quar = blockIdx.x & 3;
    const int tid  = threadIdx.x;
    const int warp = tid >> 5, lane = tid & 31;
    const int d0 = quar * Qn, d1 = d0 + Qn;

    if (tid < On * 4) ((float*)s_bx)[tid] = boxes[b * On * 4 + tid];
    if (tid < On)     s_lab[tid] = labels[b * On + tid];
    __syncthreads();
    if (tid < On) s_area[tid] = (s_bx[tid][2] - s_bx[tid][0]) * (s_bx[tid][3] - s_bx[tid][1]);
    __syncthreads();

    float ln[On], ld[On]; int li[On];
#pragma unroll
    for (int o = 0; o < On; o++) { ln[o] = -1.f; ld[o] = 1.f; li[o] = 0x7fffffff; }

    for (int d = d0 + tid; d < d1; d += 512) {
        float4 db = ((const float4*)dboxes)[d];
        float dx1 = db.x - db.z * 0.5f, dy1 = db.y - db.w * 0.5f;
        float dx2 = db.x + db.z * 0.5f, dy2 = db.y + db.w * 0.5f;
        float darea = db.z * db.w;
        float bn = -1.f, bd_ = 1.f; int besto = 0;
#pragma unroll
        for (int o = 0; o < On; o++) {
            float ix = fminf(s_bx[o][2], dx2) - fmaxf(s_bx[o][0], dx1);
            float iy = fminf(s_bx[o][3], dy2) - fmaxf(s_bx[o][1], dy1);
            ix = fmaxf(ix, 0.f); iy = fmaxf(iy, 0.f);
            float inter = ix * iy;
            float uni = s_area[o] + darea - inter;
            if (inter * bd_ > bn * uni) { bn = inter; bd_ = uni; besto = o; }   // first-max over o
            if (inter * ld[o] > ln[o] * uni) { ln[o] = inter; ld[o] = uni; li[o] = d; } // first-max over d
        }
        g_obj[b * Dn + d] = (unsigned char)besto;
        g_lab[b * Dn + d] = (2.f * bn >= bd_) ? (unsigned char)s_lab[besto] : 0;
    }

    // block-level per-object best (tie -> smaller default index)
#pragma unroll
    for (int o = 0; o < On; o++) {
        float vn = ln[o], vd = ld[o]; int vi = li[o];
        for (int off = 16; off; off >>= 1) {
            float on_ = __shfl_down_sync(0xffffffffu, vn, off);
            float od_ = __shfl_down_sync(0xffffffffu, vd, off);
            int   oi  = __shfl_down_sync(0xffffffffu, vi, off);
            float a = on_ * vd, c = vn * od_;
            if (a > c || (a == c && oi < vi)) { vn = on_; vd = od_; vi = oi; }
        }
        if (lane == 0) { s_redn[o * 16 + warp] = vn; s_redd[o * 16 + warp] = vd; s_redi[o * 16 + warp] = vi; }
    }
    __syncthreads();
    if (tid < On) {
        float vn = s_redn[tid * 16], vd = s_redd[tid * 16]; int vi = s_redi[tid * 16];
        for (int w = 1; w < 16; w++) {
            float on_ = s_redn[tid * 16 + w], od_ = s_redd[tid * 16 + w];
            int oi = s_redi[tid * 16 + w];
            float a = on_ * vd, c = vn * od_;
            if (a > c || (a == c && oi < vi)) { vn = on_; vd = od_; vi = oi; }
        }
        float iou = vn / vd;   // 16 divisions per block total
        unsigned long long pk = ((unsigned long long)__float_as_uint(iou) << 32)
                              | (unsigned long long)(0xFFFFFFFFu - (unsigned int)vi);
        g_objbest[(b * 4 + quar) * On + tid] = pk;   // plain store
    }
}

// merge per-quarter bests + apply forced matches (sequential over objects:
// last wins, matching .at[].set semantics)
__global__ void k_force(const int* __restrict__ labels) {
    const int b = blockIdx.x;
    if (threadIdx.x == 0) {
        for (int o = 0; o < On; o++) {
            unsigned long long pk = g_objbest[(b * 4 + 0) * On + o];
#pragma unroll
            for (int q = 1; q < 4; q++) {
                unsigned long long pq = g_objbest[(b * 4 + q) * On + o];
                if (pq > pk) pk = pq;    // tie impossible across disjoint d ranges
            }
            int d = (int)(0xFFFFFFFFu - (unsigned int)(pk & 0xFFFFFFFFull));
            g_obj[b * Dn + d] = (unsigned char)o;
            g_lab[b * Dn + d] = (unsigned char)labels[b * On + o];
        }
    }
}

// PURE streaming logsumexp kernel (measured shape: 32.6us @ 5.7TB/s).
// Stores negce0 = lse - p[0] (= exact ce for negatives; positives fixed in topk).
// No atomics, no match dependency, no branches in the epilogue.
__global__ __launch_bounds__(256) void k_ce(const float* __restrict__ cls) {
    const int tid = threadIdx.x;
    const int warp = tid >> 5, lane = tid & 31;
    const int group = lane >> 3, sub = lane & 7;
    const int bd = (blockIdx.x * 8 + warp) * 4 + group;   // grid sized exactly
    const float LOG2E = 1.4426950408889634f;
    const float* p = cls + bd * Cn;

    float first = p[sub];                  // k=0 element; for sub0 this IS p[0]
    float acc = ex2f(first * LOG2E);
#pragma unroll
    for (int k = 1; k < 10; k++)
        acc += ex2f(p[k * 8 + sub] * LOG2E);
    if (sub == 0)
        acc += ex2f(p[80] * LOG2E);
    acc += __shfl_xor_sync(0xffffffffu, acc, 4);
    acc += __shfl_xor_sync(0xffffffffu, acc, 2);
    acc += __shfl_xor_sync(0xffffffffu, acc, 1);
    if (sub == 0) g_negce[bd] = __logf(acc) - first;   // >= 0 always
}

// sparse positive fix-up: ce = negce0 + p0 - p[lab]; SmoothL1; returns 0
__device__ __forceinline__ float pos_fix(int b, int idx, float v, int lab,
                                         const float* __restrict__ cls,
                                         const float* __restrict__ locs_pred,
                                         const float* __restrict__ boxes,
                                         const float* __restrict__ dboxes,
                                         float& pos, float& loc) {
    long long cbase = (long long)(b * Dn + idx) * Cn;
    float p0 = cls[cbase];
    float xt = cls[cbase + lab];
    pos += v + p0 - xt;
    int o = g_obj[b * Dn + idx];
    float4 db = ((const float4*)dboxes)[idx];
    const float* bx = boxes + (b * On + o) * 4;
    float bx1 = bx[0], by1 = bx[1], bx2 = bx[2], by2 = bx[3];
    float cx = 0.5f * (bx1 + bx2), cy = 0.5f * (by1 + by2);
    float w = bx2 - bx1, h = by2 - by1;
    float t0 = (cx - db.x) / (db.z * 0.1f);
    float t1 = (cy - db.y) / (db.w * 0.1f);
    float t2 = logf(w / db.z) * 5.f;
    float t3 = logf(h / db.w) * 5.f;
    float4 pr = ((const float4*)locs_pred)[b * Dn + idx];
    float e0 = fabsf(pr.x - t0), e1 = fabsf(pr.y - t1);
    float e2 = fabsf(pr.z - t2), e3 = fabsf(pr.w - t3);
    loc += (e0 < 1.f ? 0.5f * e0 * e0 : e0 - 0.5f)
         + (e1 < 1.f ? 0.5f * e1 * e1 : e1 - 0.5f)
         + (e2 < 1.f ? 0.5f * e2 * e2 : e2 - 0.5f)
         + (e3 < 1.f ? 0.5f * e3 * e3 : e3 - 0.5f);
    return 0.f;
}

// per-batch: positive fix-up + npos/pos/loc sums + exact top-K via radix
// select (pass-1 hist fused into load, 8-way replicated). Plain stores only.
__global__ __launch_bounds__(1024) void k_topk(const float* __restrict__ cls,
                                               const float* __restrict__ locs_pred,
                                               const float* __restrict__ boxes,
                                               const float* __restrict__ dboxes) {
    __shared__ float s_val[Dn];
    __shared__ unsigned int s_hist[8][256];
    __shared__ unsigned int s_bin;
    __shared__ int s_cum;
    __shared__ float s_rs[32], s_ps[32], s_ls[32];
    __shared__ int   s_rc[32];
    __shared__ int   s_K;

    const int b = blockIdx.x, tid = threadIdx.x;
    const int warp = tid >> 5, lane = tid & 31;
    const int hrep = warp & 7;

    ((unsigned int*)s_hist)[tid] = 0;
    ((unsigned int*)s_hist)[tid + 1024] = 0;
    __syncthreads();

    float l_pos = 0.f, l_loc = 0.f; int l_cnt = 0;
    const float4* srcv = (const float4*)(g_negce + b * Dn);
    const uchar4* srcl = (const uchar4*)(g_lab + b * Dn);
    for (int i = tid; i < Dn / 4; i += 1024) {
        float4 v = srcv[i];
        uchar4 L = srcl[i];
        int e = i * 4;
        if (L.x) { v.x = pos_fix(b, e,     v.x, L.x, cls, locs_pred, boxes, dboxes, l_pos, l_loc); l_cnt++; }
        if (L.y) { v.y = pos_fix(b, e + 1, v.y, L.y, cls, locs_pred, boxes, dboxes, l_pos, l_loc); l_cnt++; }
        if (L.z) { v.z = pos_fix(b, e + 2, v.z, L.z, cls, locs_pred, boxes, dboxes, l_pos, l_loc); l_cnt++; }
        if (L.w) { v.w = pos_fix(b, e + 3, v.w, L.w, cls, locs_pred, boxes, dboxes, l_pos, l_loc); l_cnt++; }
        ((float4*)s_val)[i] = v;
        atomicAdd(&s_hist[hrep][__float_as_uint(v.x) >> 24], 1u);
        atomicAdd(&s_hist[hrep][__float_as_uint(v.y) >> 24], 1u);
        atomicAdd(&s_hist[hrep][__float_as_uint(v.z) >> 24], 1u);
        atomicAdd(&s_hist[hrep][__float_as_uint(v.w) >> 24], 1u);
    }
    // block-reduce npos / pos / loc
    for (int off = 16; off; off >>= 1) {
        l_cnt += __shfl_down_sync(0xffffffffu, l_cnt, off);
        l_pos += __shfl_down_sync(0xffffffffu, l_pos, off);
        l_loc += __shfl_down_sync(0xffffffffu, l_loc, off);
    }
    if (lane == 0) { s_rc[warp] = l_cnt; s_ps[warp] = l_pos; s_ls[warp] = l_loc; }
    __syncthreads();
    if (tid == 0) {
        int np = 0; float ps = 0.f, lsum = 0.f;
        for (int w = 0; w < 32; w++) { np += s_rc[w]; ps += s_ps[w]; lsum += s_ls[w]; }
        g_npos[b] = np;
        g_pos_arr[b] = ps;
        g_loc_arr[b] = lsum;
        int K = 3 * np; if (K > Dn) K = Dn;
        s_K = K;
        if (K <= 0) g_neg_arr[b] = 0.f;
    }
    __syncthreads();
    int K = s_K;
    if (K <= 0) return;

    unsigned int prefix = 0;
    int Krem = K;

    // pass-1 selection from the 8 replicated copies
    if (warp == 0) {
        unsigned int c[8]; int local = 0;
        int base = lane * 8;
#pragma unroll
        for (int k = 0; k < 8; k++) {
            unsigned int t = 0;
#pragma unroll
            for (int r = 0; r < 8; r++) t += s_hist[r][base + k];
            c[k] = t; local += (int)t;
        }
        int incl = local;
#pragma unroll
        for (int off = 1; off < 32; off <<= 1) {
            int v = __shfl_down_sync(0xffffffffu, incl, off);
            if (lane + off < 32) incl += v;
        }
        int excl = incl - local;
        if (excl < Krem && incl >= Krem) {
            int cum = excl;
#pragma unroll
            for (int j = 7; j >= 0; j--) {
                if (cum + (int)c[j] >= Krem) { s_bin = (unsigned int)(base + j); s_cum = cum; break; }
                cum += (int)c[j];
            }
        }
    }
    __syncthreads();
    Krem -= s_cum;
    prefix = (s_bin << 24);
    __syncthreads();

    // passes 2-4 over SMEM values (single histogram: few candidates match)
    for (int shift = 16; shift >= 0; shift -= 8) {
        if (tid < 256) s_hist[0][tid] = 0;
        __syncthreads();
        unsigned int hmask = 0xFFFFFFFFu << (shift + 8);
        for (int i = tid; i < Dn; i += 1024) {
            unsigned int u = __float_as_uint(s_val[i]);
            if ((u & hmask) == prefix) atomicAdd(&s_hist[0][(u >> shift) & 255u], 1u);
        }
        __syncthreads();
        if (warp == 0) {
            unsigned int c[8]; int local = 0;
            int base = lane * 8;
#pragma unroll
            for (int k = 0; k < 8; k++) { c[k] = s_hist[0][base + k]; local += (int)c[k]; }
            int incl = local;
#pragma unroll
            for (int off = 1; off < 32; off <<= 1) {
                int v = __shfl_down_sync(0xffffffffu, incl, off);
                if (lane + off < 32) incl += v;
            }
            int excl = incl - local;
            if (excl < Krem && incl >= Krem) {
                int cum = excl;
#pragma unroll
                for (int j = 7; j >= 0; j--) {
                    if (cum + (int)c[j] >= Krem) { s_bin = (unsigned int)(base + j); s_cum = cum; break; }
                    cum += (int)c[j];
                }
            }
        }
        __syncthreads();
        Krem -= s_cum;
        prefix |= (s_bin << shift);
        __syncthreads();
    }

    float kth = __uint_as_float(prefix);
    float ls = 0.f; int lc = 0;
    for (int i = tid; i < Dn; i += 1024) {
        float v = s_val[i];
        if (v > kth) { ls += v; lc++; }
    }
    for (int off = 16; off; off >>= 1) {
        ls += __shfl_down_sync(0xffffffffu, ls, off);
        lc += __shfl_down_sync(0xffffffffu, lc, off);
    }
    if (lane == 0) { s_rs[warp] = ls; s_rc[warp] = lc; }
    __syncthreads();
    if (tid == 0) {
        float ts = 0.f; int tc = 0;
        for (int w = 0; w < 32; w++) { ts += s_rs[w]; tc += s_rc[w]; }
        g_neg_arr[b] = ts + (float)(K - tc) * kth;   // plain store
    }
}

// reduce the 64 per-batch partials (2 warps) and emit the two outputs
__global__ void k_final(float* out) {
    const int t = threadIdx.x;   // 64 threads
    const int warp = t >> 5, lane = t & 31;
    __shared__ float s_l[2], s_p[2], s_n[2];
    __shared__ int   s_c[2];

    float lc = g_loc_arr[t], cp = g_pos_arr[t], cn = g_neg_arr[t];
    int   np = g_npos[t];
#pragma unroll
    for (int off = 16; off; off >>= 1) {
        lc += __shfl_down_sync(0xffffffffu, lc, off);
        cp += __shfl_down_sync(0xffffffffu, cp, off);
        cn += __shfl_down_sync(0xffffffffu, cn, off);
        np += __shfl_down_sync(0xffffffffu, np, off);
    }
    if (lane == 0) { s_l[warp] = lc; s_p[warp] = cp; s_n[warp] = cn; s_c[warp] = np; }
    __syncthreads();
    if (t == 0) {
        float L = s_l[0] + s_l[1], P = s_p[0] + s_p[1], N = s_n[0] + s_n[1];
        float f = (float)(s_c[0] + s_c[1]);
        out[0] = L / (f * 4.f);            // ALPHA = 1
        out[1] = (N + P) / f;
    }
}

extern "C" void kernel_launch(void* const* d_in, const int* in_sizes, int n_in,
                              void* d_out, int out_size) {
    const float* locs   = (const float*)d_in[0];
    const float* cls    = (const float*)d_in[1];
    const float* boxes  = (const float*)d_in[2];
    const int*   labels = (const int*)d_in[3];
    const float* dbox   = (const float*)d_in[4];

    k_match<<<4 * Bn, 512>>>(boxes, labels, dbox);
    k_force<<<Bn, 32>>>(labels);
    k_ce<<<(Bn * Dn) / 32, 256>>>(cls);                      // 17464 exact
    k_topk<<<Bn, 1024>>>(cls, locs, boxes, dbox);
    k_final<<<1, 64>>>((float*)d_out);
}